// round 13
// baseline (speedup 1.0000x reference)
#include <cuda_runtime.h>
#include <cuda.h>
#include <cstdint>
#include <cstddef>

#define BATCH   4
#define NNODE   4096
#define DF      128
#define UNITS   128
#define TILE_R  128
#define SC      128                 // s rows per chunk
#define NCHUNK  (NNODE / SC)        // 32
#define ADJ_STRIDE 132              // floats per adj smem row (TMA box0)
#define ADJ_ST_FLOATS (SC * ADJ_STRIDE)   // 16896 floats / stage
#define ZS      132                 // zsm row stride

// Combined weights (device scratch; no cudaMalloc allowed)
//   g_Wap[p*256 + 2*c + e] = Wa[2p+e][c]   (pair p = k/2, e = k&1)
__device__ float g_Wap[DF * UNITS];  // W1 + Wr@W2, pair-interleaved
__device__ float g_Wbp[DF * UNITS];  // Ws@W2, pair-interleaved
__device__ float g_Wr2[DF * UNITS];  // Wr@W2 row-major (deg==0 fixup only)

// ---------------------------------------------------------------------------
// Phase 0: weight prep. 128 blocks x 128 threads. Block i computes row i.
// ---------------------------------------------------------------------------
__global__ void prep_weights(const float* __restrict__ Wmsg,
                             const float* __restrict__ Wupd) {
    __shared__ float ws[DF];
    __shared__ float wr[DF];
    const int i = blockIdx.x;
    const int j = threadIdx.x;
    ws[j] = Wmsg[i * UNITS + j];
    wr[j] = Wmsg[(DF + i) * UNITS + j];
    __syncthreads();
    float sa = 0.f, sr = 0.f;
#pragma unroll 4
    for (int k = 0; k < DF; ++k) {
        const float w2 = Wupd[(DF + k) * UNITS + j];
        sa = fmaf(ws[k], w2, sa);
        sr = fmaf(wr[k], w2, sr);
    }
    const int pidx = (i >> 1) * 256 + (j << 1) + (i & 1);
    g_Wbp[pidx] = sa;
    g_Wr2[i * UNITS + j] = sr;
    g_Wap[pidx] = Wupd[i * UNITS + j] + sr;
}

// ---------------------------------------------------------------------------
// PTX helpers
// ---------------------------------------------------------------------------
__device__ __forceinline__ uint32_t smem_u32(const void* p) {
    uint32_t a;
    asm("{ .reg .u64 t; cvta.to.shared.u64 t, %1; cvt.u32.u64 %0, t; }"
        : "=r"(a) : "l"(p));
    return a;
}
__device__ __forceinline__ void mbar_init(uint32_t mbar, uint32_t cnt) {
    asm volatile("mbarrier.init.shared.b64 [%0], %1;" :: "r"(mbar), "r"(cnt) : "memory");
}
__device__ __forceinline__ void mbar_expect_tx(uint32_t mbar, uint32_t bytes) {
    asm volatile("mbarrier.arrive.expect_tx.shared.b64 _, [%0], %1;"
                 :: "r"(mbar), "r"(bytes) : "memory");
}
__device__ __forceinline__ void mbar_wait(uint32_t mbar, uint32_t parity) {
    uint32_t done;
    asm volatile(
        "{ .reg .pred p; mbarrier.try_wait.parity.acquire.cta.shared::cta.b64 p, [%1], %2;"
        " selp.b32 %0,1,0,p; }"
        : "=r"(done) : "r"(mbar), "r"(parity) : "memory");
    if (!done) {
        asm volatile(
            "{ .reg .pred P1;\n"
            "WL_%=: mbarrier.try_wait.parity.acquire.cta.shared::cta.b64 P1, [%0], %1, 0x989680;\n"
            "@P1 bra.uni WD_%=;\n"
            "bra.uni WL_%=;\n"
            "WD_%=: }"
            :: "r"(mbar), "r"(parity) : "memory");
    }
}
__device__ __forceinline__ void bulk_g2s(uint32_t dst, const void* src,
                                         uint32_t bytes, uint32_t mbar) {
    asm volatile(
        "cp.async.bulk.shared::cta.global.mbarrier::complete_tx::bytes [%0], [%1], %2, [%3];"
        :: "r"(dst), "l"(src), "r"(bytes), "r"(mbar) : "memory");
}
__device__ __forceinline__ void tma_load_2d(uint32_t dst, const CUtensorMap* tm,
                                            int cx, int cy, uint32_t mbar) {
    asm volatile(
        "cp.async.bulk.tensor.2d.shared::cta.global.tile.mbarrier::complete_tx::bytes "
        "[%0], [%1, {%2, %3}], [%4];"
        :: "r"(dst), "l"(tm), "r"(cx), "r"(cy), "r"(mbar) : "memory");
}
__device__ __forceinline__ void fma2(unsigned long long& d, unsigned long long a,
                                     unsigned long long b) {
    asm("fma.rn.f32x2 %0, %1, %2, %0;" : "+l"(d) : "l"(a), "l"(b));
}

// ---------------------------------------------------------------------------
// Main fused kernel. grid (32, 4), 1024 threads, 1 CTA/SM.
// dynamic smem: 3 adj stages of SC*132 floats = 202,752 B + 1 KB align slack
// ---------------------------------------------------------------------------
extern __shared__ char dsmem_raw[];

__global__ __launch_bounds__(1024, 1)
void mpnn_main(const __grid_constant__ CUtensorMap tmap,
               const float* __restrict__ x,
               float* __restrict__ out) {
    __shared__ __align__(8) unsigned long long mb[4];   // 3 adj stages + 1 x
    __shared__ float degs[TILE_R];

    // TMA smem destinations must be 128B-aligned; dynamic smem base is only
    // guaranteed 16B. Align the working base to 1024.
    float* smem = (float*)(((uintptr_t)dsmem_raw + 1023) & ~(uintptr_t)1023);

    const int b   = blockIdx.y;
    const int r0  = blockIdx.x * TILE_R;
    const int tid = threadIdx.x;
    const int w    = tid >> 5;   // warp 0..31: owns r-cols r0+4w .. 4w+3
    const int lane = tid & 31;

    const float* xb = x + (size_t)b * NNODE * DF;

    const uint32_t mb_base = smem_u32(&mb[0]);
    if (tid == 0) {
        mbar_init(mb_base + 0,  1);
        mbar_init(mb_base + 8,  1);
        mbar_init(mb_base + 16, 1);
        mbar_init(mb_base + 24, 1);
        asm volatile("prefetch.tensormap [%0];" :: "l"(&tmap));
    }
    __syncthreads();

    // one TMA 2D tile per chunk: box [132 cols, 128 rows] -> stride-132 smem rows
    auto issue_chunk = [&](int c) {
        if (tid == 0) {
            const int st = c % 3;
            const uint32_t mbar = mb_base + st * 8;
            mbar_expect_tx(mbar, ADJ_ST_FLOATS * 4);   // 67584 B
            tma_load_2d(smem_u32(&smem[(size_t)st * ADJ_ST_FLOATS]),
                        &tmap, r0, b * NNODE + c * SC, mbar);
        }
    };

    float acc[4][4] = {};
    int   dcnt[4]   = {0, 0, 0, 0};

    // -------- phase 1: stream adj (3-stage TMA), per-r ballot scan --------
    issue_chunk(0);
    issue_chunk(1);
    issue_chunk(2);

    for (int c = 0; c < NCHUNK; ++c) {
        const int st = c % 3;
        mbar_wait(mb_base + st * 8, (c / 3) & 1);

        const float* cur = smem + (size_t)st * ADJ_ST_FLOATS;
        const int s_chunk = c << 7;

#pragma unroll
        for (int sb = 0; sb < SC; sb += 32) {
            const float4 av = *reinterpret_cast<const float4*>(
                &cur[(sb + lane) * ADJ_STRIDE + (w << 2)]);
            const int s_base = s_chunk + sb;

            // set bit == adj entry is EXACTLY 1.0 -> aggregate is a plain add
            unsigned m0 = __ballot_sync(0xffffffffu, av.x != 0.0f);
            unsigned m1 = __ballot_sync(0xffffffffu, av.y != 0.0f);
            unsigned m2 = __ballot_sync(0xffffffffu, av.z != 0.0f);
            unsigned m3 = __ballot_sync(0xffffffffu, av.w != 0.0f);
            dcnt[0] += __popc(m0);
            dcnt[1] += __popc(m1);
            dcnt[2] += __popc(m2);
            dcnt[3] += __popc(m3);

#define SCAN_COMP(MASK, RP)                                                          \
            while (MASK) {                                                           \
                const int i = __ffs(MASK) - 1; MASK &= MASK - 1;                     \
                const float4 xv = *reinterpret_cast<const float4*>(                  \
                    &xb[(size_t)(s_base + i) * DF + (lane << 2)]);                   \
                acc[RP][0] += xv.x; acc[RP][1] += xv.y;                              \
                acc[RP][2] += xv.z; acc[RP][3] += xv.w;                              \
            }
            SCAN_COMP(m0, 0)
            SCAN_COMP(m1, 1)
            SCAN_COMP(m2, 2)
            SCAN_COMP(m3, 3)
#undef SCAN_COMP
        }
        __syncthreads();              // all readers of stage st done before refill
        if (c + 3 < NCHUNK) issue_chunk(c + 3);
    }

    // -------- phase boundary: xsm in stage-0 region, zsm in stage-1 region ------
    float* xsm = smem;                          // [128][128] floats, [0, 16384)
    float* zsm = smem + ADJ_ST_FLOATS;          // [128][132] floats, stage-1 region

    if (tid == 0) {
        mbar_expect_tx(mb_base + 24, TILE_R * DF * 4);  // 65536 B, contiguous
        bulk_g2s(smem_u32(xsm), xb + (size_t)r0 * DF, TILE_R * DF * 4, mb_base + 24);
    }

    // dcnt is warp-uniform (popc of full ballots)
#pragma unroll
    for (int rp = 0; rp < 4; ++rp) {
        const int r = (w << 2) + rp;
        const float d = (float)dcnt[rp];
        const float inv = (dcnt[rp] > 0) ? (1.0f / d) : 0.0f;
        float4 zv;
        zv.x = acc[rp][0] * inv; zv.y = acc[rp][1] * inv;
        zv.z = acc[rp][2] * inv; zv.w = acc[rp][3] * inv;
        *reinterpret_cast<float4*>(&zsm[(size_t)r * ZS + (lane << 2)]) = zv;
        if (lane == 0) degs[r] = d;
    }

    mbar_wait(mb_base + 24, 0);
    __syncthreads();

    // -------- phase 2: out = xsm @ Wa + zsm @ Wb  (k-pair packed f32x2) --------
    const int rg  = w >> 2;                 // 0..7 -> rows 16*rg .. +16
    const int col = ((w & 3) << 5) + lane;  // 0..127

    unsigned long long cacc[16];
#pragma unroll
    for (int i = 0; i < 16; ++i) cacc[i] = 0ull;

#pragma unroll 1
    for (int pass = 0; pass < 2; ++pass) {
        const float* A  = pass ? zsm : xsm;
        const int    As = pass ? ZS : DF;
        const float* Wp = pass ? g_Wbp : g_Wap;
#pragma unroll 4
        for (int k = 0; k < DF; k += 4) {
            const unsigned long long w0 = *reinterpret_cast<const unsigned long long*>(
                &Wp[(size_t)(k >> 1) * 256 + (col << 1)]);
            const unsigned long long w1 = *reinterpret_cast<const unsigned long long*>(
                &Wp[(size_t)((k >> 1) + 1) * 256 + (col << 1)]);
#pragma unroll
            for (int i = 0; i < 16; ++i) {
                const ulonglong2 av = *reinterpret_cast<const ulonglong2*>(
                    &A[(size_t)(16 * rg + i) * As + k]);   // warp-uniform broadcast
                fma2(cacc[i], av.x, w0);
                fma2(cacc[i], av.y, w1);
            }
        }
    }

    float* outb = out + ((size_t)b * NNODE + r0) * UNITS;
#pragma unroll
    for (int i = 0; i < 16; ++i) {
        const int r = 16 * rg + i;
        unsigned lo, hi;
        asm("mov.b64 {%0, %1}, %2;" : "=r"(lo), "=r"(hi) : "l"(cacc[i]));
        float o = __uint_as_float(lo) + __uint_as_float(hi);

        if (degs[r] == 0.0f) {
            float corr = 0.0f;
            for (int k = 0; k < DF; ++k)
                corr = fmaf(xsm[(size_t)r * DF + k], g_Wr2[k * UNITS + col], corr);
            o -= corr;
        }
        outb[(size_t)r * UNITS + col] = o;
    }
}

// ---------------------------------------------------------------------------
// Launch: build adj tensor map via driver entry point (no -lcuda needed)
// ---------------------------------------------------------------------------
typedef CUresult (CUDAAPI *tmap_encode_fn)(
    CUtensorMap*, CUtensorMapDataType, cuuint32_t, void*,
    const cuuint64_t*, const cuuint64_t*, const cuuint32_t*, const cuuint32_t*,
    CUtensorMapInterleave, CUtensorMapSwizzle, CUtensorMapL2promotion,
    CUtensorMapFloatOOBfill);

extern "C" void kernel_launch(void* const* d_in, const int* in_sizes, int n_in,
                              void* d_out, int out_size) {
    (void)in_sizes; (void)n_in; (void)out_size;
    const float* x    = (const float*)d_in[0];
    const float* adj  = (const float*)d_in[1];
    const float* Wmsg = (const float*)d_in[2];
    const float* Wupd = (const float*)d_in[3];
    float* out = (float*)d_out;

    // adj as 2D tensor: inner dim r (4096 f32), outer dim batch*s (16384 rows)
    void* fn = nullptr;
    cudaDriverEntryPointQueryResult qres;
    cudaGetDriverEntryPointByVersion("cuTensorMapEncodeTiled", &fn, 12050,
                                     cudaEnableDefault, &qres);
    CUtensorMap tmap;
    {
        cuuint64_t dims[2]    = {NNODE, (cuuint64_t)BATCH * NNODE};
        cuuint64_t strides[1] = {NNODE * sizeof(float)};
        cuuint32_t box[2]     = {ADJ_STRIDE, SC};       // 132 x 128 (OOB cols zero-fill)
        cuuint32_t estr[2]    = {1, 1};
        ((tmap_encode_fn)fn)(&tmap, CU_TENSOR_MAP_DATA_TYPE_FLOAT32, 2,
                             (void*)adj, dims, strides, box, estr,
                             CU_TENSOR_MAP_INTERLEAVE_NONE,
                             CU_TENSOR_MAP_SWIZZLE_NONE,
                             CU_TENSOR_MAP_L2_PROMOTION_L2_128B,
                             CU_TENSOR_MAP_FLOAT_OOB_FILL_NONE);
    }

    prep_weights<<<128, 128>>>(Wmsg, Wupd);

    const size_t shbytes = (size_t)3 * ADJ_ST_FLOATS * sizeof(float) + 1024;
    cudaFuncSetAttribute(mpnn_main, cudaFuncAttributeMaxDynamicSharedMemorySize,
                         (int)shbytes);
    mpnn_main<<<dim3(NNODE / TILE_R, BATCH), 1024, shbytes>>>(tmap, x, out);
}